// round 10
// baseline (speedup 1.0000x reference)
#include <cuda_runtime.h>
#include <cuda_bf16.h>
#include <stdint.h>
#include <math.h>

// Problem constants
#define Bn  64
#define Sn  512
#define INn 512
#define Hn  1024
#define G3  3072          // 3*H
#define SB  32768         // S*B

#define NRBLK 128         // recurrence grid: 2 dirs x 64 tiles (16 j-cols, 48 W rows)
#define NBAR  64          // barrier domain: blocks per direction
#define RB    48
#define RTHREADS 512

// ----------------------------------------------------------------------------
// Device scratch (static — no allocations allowed)
// ----------------------------------------------------------------------------
__device__ __nv_bfloat16 g_x_hi[(size_t)SB * INn];
__device__ __nv_bfloat16 g_x_lo[(size_t)SB * INn];
__device__ float g_gi[(size_t)2 * SB * G3];
__device__ __nv_bfloat16 g_h0_hi[(size_t)2 * SB * Hn];
__device__ __nv_bfloat16 g_h0_lo[(size_t)2 * SB * Hn];
// hA double-buffered by step parity: [2 parity][2 dir][Bn][Hn]
__device__ __nv_bfloat16 g_hA_hi[2 * 2 * Bn * Hn];
__device__ __nv_bfloat16 g_hA_lo[2 * 2 * Bn * Hn];
__device__ float g_bias0[2 * G3];
__device__ float g_bias1[2 * G3];

__device__ __nv_bfloat16 g_wih0_hi[(size_t)2 * G3 * INn];
__device__ __nv_bfloat16 g_wih0_lo[(size_t)2 * G3 * INn];
__device__ __nv_bfloat16 g_wih1_hi[(size_t)2 * G3 * Hn];
__device__ __nv_bfloat16 g_wih1_lo[(size_t)2 * G3 * Hn];
// W_hh stored ROW-PERMUTED: row p = tile*48 + gate*16 + jj  <-  src row gate*H + tile*16 + jj
__device__ __nv_bfloat16 g_whh0_hi[(size_t)2 * G3 * Hn];
__device__ __nv_bfloat16 g_whh0_lo[(size_t)2 * G3 * Hn];
__device__ __nv_bfloat16 g_whh1_hi[(size_t)2 * G3 * Hn];
__device__ __nv_bfloat16 g_whh1_lo[(size_t)2 * G3 * Hn];

// per-direction barrier state
__device__ volatile unsigned g_bar_gen[2];
__device__ unsigned g_bar_cnt[2];

// ----------------------------------------------------------------------------
// cp.async / ldmatrix helpers
// ----------------------------------------------------------------------------
__device__ __forceinline__ void cp16(void* dst, const void* src) {
    uint32_t d = (uint32_t)__cvta_generic_to_shared(dst);
    asm volatile("cp.async.cg.shared.global [%0], [%1], 16;\n" :: "r"(d), "l"(src));
}
#define CP_COMMIT() asm volatile("cp.async.commit_group;\n")
#define CP_WAIT0()  asm volatile("cp.async.wait_group 0;\n")
#define CP_WAIT1()  asm volatile("cp.async.wait_group 1;\n")
#define CP_WAIT2()  asm volatile("cp.async.wait_group 2;\n")

__device__ __forceinline__ void ldsm4(uint32_t r[4], uint32_t saddr) {
    asm volatile("ldmatrix.sync.aligned.m8n8.x4.shared.b16 {%0,%1,%2,%3}, [%4];"
                 : "=r"(r[0]), "=r"(r[1]), "=r"(r[2]), "=r"(r[3]) : "r"(saddr));
}
__device__ __forceinline__ void ldsm2(uint32_t r[2], uint32_t saddr) {
    asm volatile("ldmatrix.sync.aligned.m8n8.x2.shared.b16 {%0,%1}, [%2];"
                 : "=r"(r[0]), "=r"(r[1]) : "r"(saddr));
}

__device__ __forceinline__ void mma_bf16(float c[4], const uint32_t a[4],
                                         uint32_t b0, uint32_t b1) {
    asm("mma.sync.aligned.m16n8k16.row.col.f32.bf16.bf16.f32 "
        "{%0,%1,%2,%3}, {%4,%5,%6,%7}, {%8,%9}, {%0,%1,%2,%3};\n"
        : "+f"(c[0]), "+f"(c[1]), "+f"(c[2]), "+f"(c[3])
        : "r"(a[0]), "r"(a[1]), "r"(a[2]), "r"(a[3]), "r"(b0), "r"(b1));
}

__device__ __forceinline__ float fsigmoid(float x) {
    return 1.0f / (1.0f + __expf(-x));
}

// ----------------------------------------------------------------------------
// Prep: all weight splits (+ W_hh permutation) + biases, one kernel
// ----------------------------------------------------------------------------
__device__ __forceinline__ void split_at(const float* src, size_t si,
                                         __nv_bfloat16* hi, __nv_bfloat16* lo, size_t di) {
    float v = src[si];
    __nv_bfloat16 h = __float2bfloat16(v);
    hi[di] = h;
    lo[di] = __float2bfloat16(v - __bfloat162float(h));
}

__global__ void k_prep(
    const float* __restrict__ wih0f, const float* __restrict__ wih0b,
    const float* __restrict__ wih1f, const float* __restrict__ wih1b,
    const float* __restrict__ whh0f, const float* __restrict__ whh0b,
    const float* __restrict__ whh1f, const float* __restrict__ whh1b,
    const float* __restrict__ bih0f, const float* __restrict__ bhh0f,
    const float* __restrict__ bih0b, const float* __restrict__ bhh0b,
    const float* __restrict__ bih1f, const float* __restrict__ bhh1f,
    const float* __restrict__ bih1b, const float* __restrict__ bhh1b)
{
    const int seg = blockIdx.y;
    const int stride = gridDim.x * blockDim.x;
    int i0 = blockIdx.x * blockDim.x + threadIdx.x;

    if (seg == 0) {
        for (int i = i0; i < G3 * INn; i += stride)
            split_at(wih0f, i, g_wih0_hi, g_wih0_lo, i);
    } else if (seg == 1) {
        for (int i = i0; i < G3 * INn; i += stride) {
            int n = i / INn, k = i % INn;
            split_at(wih0b, (size_t)n * INn + (INn - 1 - k),
                     g_wih0_hi, g_wih0_lo, (size_t)G3 * INn + i);
        }
    } else if (seg == 2) {
        for (int i = i0; i < G3 * Hn; i += stride)
            split_at(wih1f, i, g_wih1_hi, g_wih1_lo, i);
    } else if (seg == 3) {
        for (int i = i0; i < G3 * Hn; i += stride)
            split_at(wih1b, i, g_wih1_hi, g_wih1_lo, (size_t)G3 * Hn + i);
    } else if (seg <= 7) {
        const float* src = (seg == 4) ? whh0f : (seg == 5) ? whh0b
                         : (seg == 6) ? whh1f : whh1b;
        __nv_bfloat16* hi = (seg <= 5) ? g_whh0_hi : g_whh1_hi;
        __nv_bfloat16* lo = (seg <= 5) ? g_whh0_lo : g_whh1_lo;
        size_t doff = (seg == 5 || seg == 7) ? (size_t)G3 * Hn : 0;
        for (int i = i0; i < G3 * Hn; i += stride) {
            int prow = i >> 10, k = i & 1023;
            int tile = prow / 48, gate = (prow % 48) >> 4, jj = prow & 15;
            size_t srow = (size_t)gate * Hn + tile * 16 + jj;
            split_at(src, srow * Hn + k, hi, lo, doff + i);
        }
    } else {
        for (int i = i0; i < G3; i += stride) {
            float add = (i < 2 * Hn) ? 1.0f : 0.0f;
            g_bias0[i]      = bih0f[i] + add * bhh0f[i];
            g_bias0[G3 + i] = bih0b[i] + add * bhh0b[i];
            g_bias1[i]      = bih1f[i] + add * bhh1f[i];
            g_bias1[G3 + i] = bih1b[i] + add * bhh1b[i];
        }
    }
}

__global__ void k_xT_split(const float* __restrict__ x,
                           __nv_bfloat16* __restrict__ hi,
                           __nv_bfloat16* __restrict__ lo) {
    size_t total = (size_t)Bn * Sn * INn;
    for (size_t i = (size_t)blockIdx.x * blockDim.x + threadIdx.x; i < total;
         i += (size_t)gridDim.x * blockDim.x) {
        int k = (int)(i % INn);
        size_t tmp = i / INn;
        int s = (int)(tmp % Sn);
        int b = (int)(tmp / Sn);
        float v = x[i];
        __nv_bfloat16 h = __float2bfloat16(v);
        size_t o = ((size_t)s * Bn + b) * INn + k;
        hi[o] = h;
        lo[o] = __float2bfloat16(v - __bfloat162float(h));
    }
}

// ----------------------------------------------------------------------------
// Batched split-bf16 GEMM, 128x64 tile, 3-stage cp.async, ldmatrix fragments.
// ----------------------------------------------------------------------------
__global__ __launch_bounds__(256) void k_gemm(
    const __nv_bfloat16* __restrict__ Ahi, const __nv_bfloat16* __restrict__ Alo,
    size_t aStrZ,
    const __nv_bfloat16* __restrict__ Whi, const __nv_bfloat16* __restrict__ Wlo,
    size_t wStrZ,
    const float* __restrict__ bias, size_t bStrZ,
    float* __restrict__ C, size_t cStrZ,
    int N, int K)
{
    const int z = blockIdx.z;
    Ahi += (size_t)z * aStrZ;  Alo += (size_t)z * aStrZ;
    Whi += (size_t)z * wStrZ;  Wlo += (size_t)z * wStrZ;
    const float* biasz = bias ? (bias + (size_t)z * bStrZ) : nullptr;
    C += (size_t)z * cStrZ;

    const int m0 = blockIdx.y * 128;
    const int n0 = blockIdx.x * 64;

    extern __shared__ __align__(16) __nv_bfloat16 sm[];
    __nv_bfloat16* sA = sm;                     // [3][2][128][40]
    __nv_bfloat16* sW = sm + 3 * 2 * 128 * 40;  // [3][2][64][40]
    const uint32_t sAaddr = (uint32_t)__cvta_generic_to_shared(sA);
    const uint32_t sWaddr = (uint32_t)__cvta_generic_to_shared(sW);

    const int tid  = threadIdx.x;
    const int lane = tid & 31;
    const int warp = tid >> 5;
    const int wm = warp & 3;
    const int wn = warp >> 2;
    const int g  = lane >> 2;
    const int tq = lane & 3;

    const int arow = tid >> 1;
    const int acol = (tid & 1) * 16;
    const int wrow = tid >> 2;
    const int wcol = (tid & 3) * 8;
    const int lrow  = lane & 15;
    const int lcol8 = (lane >> 4) * 8;

    float acc[2][4][4];
#pragma unroll
    for (int a = 0; a < 2; a++)
#pragma unroll
        for (int b = 0; b < 4; b++)
#pragma unroll
            for (int c = 0; c < 4; c++) acc[a][b][c] = 0.0f;

    const int nk = K / 32;

    auto copy_chunk = [&](int ci, int st) {
        const int k0 = ci * 32;
        const size_t ao = (size_t)(m0 + arow) * K + k0 + acol;
        __nv_bfloat16* dA0 = sA + ((st * 2 + 0) * 128 + arow) * 40 + acol;
        __nv_bfloat16* dA1 = sA + ((st * 2 + 1) * 128 + arow) * 40 + acol;
        cp16(dA0,     Ahi + ao);
        cp16(dA0 + 8, Ahi + ao + 8);
        cp16(dA1,     Alo + ao);
        cp16(dA1 + 8, Alo + ao + 8);
        const size_t wo = (size_t)(n0 + wrow) * K + k0 + wcol;
        cp16(sW + ((st * 2 + 0) * 64 + wrow) * 40 + wcol, Whi + wo);
        cp16(sW + ((st * 2 + 1) * 64 + wrow) * 40 + wcol, Wlo + wo);
        CP_COMMIT();
    };

    copy_chunk(0, 0);
    copy_chunk(1, 1);

    for (int ci = 0; ci < nk; ci++) {
        const int st = ci % 3;
        CP_WAIT1();
        __syncthreads();
        if (ci + 2 < nk) copy_chunk(ci + 2, (ci + 2) % 3);
        else CP_COMMIT();

#pragma unroll
        for (int kk = 0; kk < 32; kk += 16) {
            uint32_t ah[2][4], al[2][4];
#pragma unroll
            for (int ms = 0; ms < 2; ms++) {
                uint32_t base = ((st * 2 + 0) * 128 + wm * 32 + ms * 16 + lrow) * 40
                                + kk + lcol8;
                ldsm4(ah[ms], sAaddr + base * 2);
                base = ((st * 2 + 1) * 128 + wm * 32 + ms * 16 + lrow) * 40 + kk + lcol8;
                ldsm4(al[ms], sAaddr + base * 2);
            }
            uint32_t bh01[4], bl01[4], bh23[4], bl23[4];
            {
                uint32_t b = ((st * 2 + 0) * 64 + wn * 32 + lrow) * 40 + kk + lcol8;
                ldsm4(bh01, sWaddr + b * 2);
                b = ((st * 2 + 1) * 64 + wn * 32 + lrow) * 40 + kk + lcol8;
                ldsm4(bl01, sWaddr + b * 2);
                b = ((st * 2 + 0) * 64 + wn * 32 + 16 + lrow) * 40 + kk + lcol8;
                ldsm4(bh23, sWaddr + b * 2);
                b = ((st * 2 + 1) * 64 + wn * 32 + 16 + lrow) * 40 + kk + lcol8;
                ldsm4(bl23, sWaddr + b * 2);
            }
#pragma unroll
            for (int ms = 0; ms < 2; ms++) {
                mma_bf16(acc[ms][0], ah[ms], bh01[0], bh01[2]);
                mma_bf16(acc[ms][0], ah[ms], bl01[0], bl01[2]);
                mma_bf16(acc[ms][0], al[ms], bh01[0], bh01[2]);
                mma_bf16(acc[ms][1], ah[ms], bh01[1], bh01[3]);
                mma_bf16(acc[ms][1], ah[ms], bl01[1], bl01[3]);
                mma_bf16(acc[ms][1], al[ms], bh01[1], bh01[3]);
                mma_bf16(acc[ms][2], ah[ms], bh23[0], bh23[2]);
                mma_bf16(acc[ms][2], ah[ms], bl23[0], bl23[2]);
                mma_bf16(acc[ms][2], al[ms], bh23[0], bh23[2]);
                mma_bf16(acc[ms][3], ah[ms], bh23[1], bh23[3]);
                mma_bf16(acc[ms][3], ah[ms], bl23[1], bl23[3]);
                mma_bf16(acc[ms][3], al[ms], bh23[1], bh23[3]);
            }
        }
    }

#pragma unroll
    for (int ms = 0; ms < 2; ms++)
#pragma unroll
        for (int nf = 0; nf < 4; nf++) {
            int col = n0 + wn * 32 + nf * 8 + tq * 2;
            float b0 = biasz ? biasz[col]     : 0.0f;
            float b1 = biasz ? biasz[col + 1] : 0.0f;
            int row = m0 + wm * 32 + ms * 16 + g;
            float* c0 = C + (size_t)row * N + col;
            c0[0] = acc[ms][nf][0] + b0;
            c0[1] = acc[ms][nf][1] + b1;
            float* c1 = C + (size_t)(row + 8) * N + col;
            c1[0] = acc[ms][nf][2] + b0;
            c1[1] = acc[ms][nf][3] + b1;
        }
}

// ----------------------------------------------------------------------------
// Per-direction grid barrier (64 blocks per domain)
// ----------------------------------------------------------------------------
__device__ __forceinline__ void grid_barrier(int dir) {
    __syncthreads();
    if (threadIdx.x == 0) {
        unsigned gen = g_bar_gen[dir];
        __threadfence();
        if (atomicAdd(&g_bar_cnt[dir], 1) == NBAR - 1) {
            g_bar_cnt[dir] = 0;
            __threadfence();
            g_bar_gen[dir] = gen + 1;
        } else {
            while (g_bar_gen[dir] == gen) { __nanosleep(32); }
        }
        __threadfence();
    }
    __syncthreads();
}

// ----------------------------------------------------------------------------
// Gate-fused persistent recurrence, 512 threads (16 warps).
// Warp layout: wk(2 k16-slices per 32-chunk) x wm(4x16 rows) x wn(2x24 cols).
// SOFTWARE-PIPELINED fragments: mma(ci) consumes registers loaded at iter ci-1;
// per iter: sync -> issue copy(ci+3) -> mma(ci) -> wait_group 1 -> frag_load(ci+1).
// hA double-buffered by step parity (fixes cross-block read/write race).
// Hidden state h in registers; gi prefetched via __ldg per step.
// smem 229,376 B: W resident hi/lo [48][1024] swz + A ring [4][2][64][32] swz.
// sC partials (stride 48) alias the A ring in the epilogue.
// ----------------------------------------------------------------------------
__global__ __launch_bounds__(RTHREADS) void k_recur(
    const __nv_bfloat16* __restrict__ Whi,  // [2][G3][Hn] permuted rows
    const __nv_bfloat16* __restrict__ Wlo,
    const float* __restrict__ gi,           // [2][SB][G3]
    __nv_bfloat16* __restrict__ hAhi,       // [2 par][2 dir][B][H]
    __nv_bfloat16* __restrict__ hAlo,
    const float* __restrict__ bhh_f, const float* __restrict__ bhh_b,
    __nv_bfloat16* __restrict__ h0hi,       // layer0: [2][SB][H]; else null
    __nv_bfloat16* __restrict__ h0lo,
    float* __restrict__ out)                // layer1: output; else null
{
    extern __shared__ __align__(16) char sm_raw[];
    __nv_bfloat16* sWhi = reinterpret_cast<__nv_bfloat16*>(sm_raw);   // [48][1024] swz
    __nv_bfloat16* sWlo = sWhi + RB * 1024;
    __nv_bfloat16* sAb  = sWlo + RB * 1024;      // [4][2][64][32] swz
    float* sC = reinterpret_cast<float*>(sAb);   // alias: [2][64][48]
    const uint32_t sAaddr  = (uint32_t)__cvta_generic_to_shared(sAb);
    const uint32_t sWhaddr = (uint32_t)__cvta_generic_to_shared(sWhi);
    const uint32_t sWladdr = (uint32_t)__cvta_generic_to_shared(sWlo);

    const int tid  = threadIdx.x;
    const int dir  = blockIdx.x >> 6;
    const int tile = blockIdx.x & 63;
    const int j0   = tile * 16;
    const int p0   = tile * RB;
    const int HAS  = 2 * Bn * Hn;   // parity stride

    const __nv_bfloat16* WhiD = Whi + (size_t)dir * G3 * Hn;
    const __nv_bfloat16* WloD = Wlo + (size_t)dir * G3 * Hn;
    const float* bhh = dir ? bhh_b : bhh_f;

    const int lane = tid & 31;
    const int warp = tid >> 5;
    const int wk = warp >> 3;        // k16 slice within 32-chunk
    const int w8 = warp & 7;
    const int wm = w8 & 3;           // 16 M rows
    const int wn = w8 >> 2;          // 24 W cols
    const int kk = wk * 16;
    const int lrow   = lane & 15;
    const int lq     = lane >> 4;    // 0/1 (8-col half)
    const int lrow2  = lane & 7;
    const int lq2    = (lane >> 3) & 1;
    const int g  = lane >> 2;
    const int tq = lane & 3;

    // A-copy mapping: 512 threads -> one cp16 per 32-chunk
    const int cp_p   = tid >> 8;           // plane hi/lo
    const int cp_row = (tid >> 2) & 63;    // batch row
    const int cp_q   = tid & 3;            // 16B chunk within 32-col row
    const int cp_swz = cp_q ^ ((cp_row >> 1) & 3);

    // gate-phase mapping
    const int gj = tid & 15;
    const int gb = tid >> 4;               // 0..31
    const float bias_n = bhh[2 * Hn + j0 + gj];

    // ---- load resident W slice (swizzled, no pad) ----
    for (int i = tid; i < RB * 128; i += RTHREADS) {
        int row = i >> 7;
        int q   = i & 127;
        int dq  = q ^ (row & 7);
        const size_t off = (size_t)(p0 + row) * Hn + q * 8;
        cp16(&sWhi[row * 1024 + dq * 8], WhiD + off);
        cp16(&sWlo[row * 1024 + dq * 8], WloD + off);
    }
    CP_COMMIT();

    // ---- zero split hidden state (both parities) ----
    for (int i = tid; i < Bn * 16; i += RTHREADS) {
        int b = i >> 4, j = i & 15;
        int idx = dir * (Bn * Hn) + b * Hn + j0 + j;
        hAhi[idx] = __float2bfloat16(0.0f);
        hAlo[idx] = __float2bfloat16(0.0f);
        hAhi[HAS + idx] = __float2bfloat16(0.0f);
        hAlo[HAS + idx] = __float2bfloat16(0.0f);
    }
    CP_WAIT0();
    grid_barrier(dir);

    // hidden state in registers: this thread owns (b = gb + e*32, j = j0 + gj)
    float h_reg[2] = {0.0f, 0.0f};

    // per-step A source pointers (parity-dependent, set in step loop)
    const __nv_bfloat16* pAhi = nullptr;
    const __nv_bfloat16* pAlo = nullptr;

    auto copyA = [&](int ci) {
        const int st = ci & 3;
        const __nv_bfloat16* src = cp_p ? pAlo : pAhi;
        cp16(&sAb[((st * 2 + cp_p) * 64 + cp_row) * 32 + cp_swz * 8],
             src + (size_t)cp_row * Hn + ci * 32 + cp_q * 8);
        CP_COMMIT();
    };

    // double-buffered fragments
    uint32_t fah[2][4], fal[2][4], fbh01[2][4], fbl01[2][4], fbh2[2][2], fbl2[2][2];

    auto frag_load = [&](int ci, int pb) {
        const int st = ci & 3;
        {
            const int r = wm * 16 + lrow;
            const int c = (kk >> 3) + lq;
            const int swz = c ^ ((r >> 1) & 3);
            ldsm4(fah[pb], sAaddr + (((st * 2 + 0) * 64 + r) * 32 + swz * 8) * 2);
            ldsm4(fal[pb], sAaddr + (((st * 2 + 1) * 64 + r) * 32 + swz * 8) * 2);
        }
        const int kg = ci * 32 + kk;
        {
            const int r = wn * 24 + lrow;
            const int c = (kg >> 3) + lq;
            uint32_t off = (r * 1024 + (c ^ (r & 7)) * 8) * 2;
            ldsm4(fbh01[pb], sWhaddr + off);
            ldsm4(fbl01[pb], sWladdr + off);
            const int r2 = wn * 24 + 16 + lrow2;
            const int c2 = (kg >> 3) + lq2;
            off = (r2 * 1024 + (c2 ^ (r2 & 7)) * 8) * 2;
            ldsm2(fbh2[pb], sWhaddr + off);
            ldsm2(fbl2[pb], sWladdr + off);
        }
    };

    for (int t = 0; t < Sn; ++t) {
        const int par_r = t & 1;
        const int par_w = par_r ^ 1;
        pAhi = hAhi + (size_t)par_r * HAS + (size_t)dir * Bn * Hn;
        pAlo = hAlo + (size_t)par_r * HAS + (size_t)dir * Bn * Hn;

        float acc[3][4];
#pragma unroll
        for (int i = 0; i < 3; i++)
#pragma unroll
            for (int j = 0; j < 4; j++) acc[i][j] = 0.0f;

        // prologue: fill 3 ring stages
        copyA(0);
        copyA(1);
        copyA(2);

        // gi gate-input prefetch: issued now, consumed after the K loop
        float gir[2][3];
        {
            const float* giT = gi + (size_t)dir * SB * G3 + (size_t)t * Bn * G3;
#pragma unroll
            for (int e = 0; e < 2; e++) {
                const float* p = giT + (size_t)(gb + e * 32) * G3 + j0 + gj;
                gir[e][0] = __ldg(p);
                gir[e][1] = __ldg(p + Hn);
                gir[e][2] = __ldg(p + 2 * Hn);
            }
        }

        CP_WAIT1();             // G0, G1 complete (pending {G2})
        __syncthreads();        // visibility of everyone's copies of stage 0
        frag_load(0, 0);

#pragma unroll 2
        for (int ci = 0; ci < 32; ci++) {
            const int pb = ci & 1;
            __syncthreads();                 // all warps aligned; stage (ci-1)&3 free
            if (ci + 3 < 32) copyA(ci + 3);  // writes stage (ci-1)&3 — safe
            else CP_COMMIT();

            // mma on fragments loaded at iter ci-1 (registers only)
            mma_bf16(acc[0], fah[pb], fbh01[pb][0], fbh01[pb][2]);
            mma_bf16(acc[0], fah[pb], fbl01[pb][0], fbl01[pb][2]);
            mma_bf16(acc[0], fal[pb], fbh01[pb][0], fbh01[pb][2]);
            mma_bf16(acc[1], fah[pb], fbh01[pb][1], fbh01[pb][3]);
            mma_bf16(acc[1], fah[pb], fbl01[pb][1], fbl01[pb][3]);
            mma_bf16(acc[1], fal[pb], fbh01[pb][1], fbh01[pb][3]);
            mma_bf16(acc[2], fah[pb], fbh2[pb][0], fbh2[pb][1]);
            mma_bf16(acc[2], fah[pb], fbl2[pb][0], fbl2[pb][1]);
            mma_bf16(acc[2], fal[pb], fbh2[pb][0], fbh2[pb][1]);

            CP_WAIT1();                      // G(ci+2) done -> next iter's reads safe
            if (ci + 1 < 32) frag_load(ci + 1, pb ^ 1);
        }

        // ---- epilogue: wk partials -> sC0/sC1 (alias A ring), stride 48 ----
        __syncthreads();
        float* sC0 = sC;
        float* sC1 = sC + 64 * 48;
        {
            float* d = wk ? sC1 : sC0;
#pragma unroll
            for (int nf = 0; nf < 3; nf++) {
                int col = wn * 24 + nf * 8 + tq * 2;
                int row = wm * 16 + g;
                d[row * 48 + col]           = acc[nf][0];
                d[row * 48 + col + 1]       = acc[nf][1];
                d[(row + 8) * 48 + col]     = acc[nf][2];
                d[(row + 8) * 48 + col + 1] = acc[nf][3];
            }
        }
        __syncthreads();

        // ---- gate update for own (dir, all b, j0+gj) ----
        __nv_bfloat16* wAhi = hAhi + (size_t)par_w * HAS + (size_t)dir * Bn * Hn;
        __nv_bfloat16* wAlo = hAlo + (size_t)par_w * HAS + (size_t)dir * Bn * Hn;
#pragma unroll
        for (int e = 0; e < 2; e++) {
            const int b = gb + e * 32;
            const float* c0 = sC0 + b * 48;
            const float* c1 = sC1 + b * 48;
            float hr  = c0[gj]      + c1[gj];
            float hz  = c0[16 + gj] + c1[16 + gj];
            float hn  = c0[32 + gj] + c1[32 + gj] + bias_n;
            float h   = h_reg[e];

            float r  = fsigmoid(gir[e][0] + hr);
            float zz = fsigmoid(gir[e][1] + hz);
            float n  = tanhf(gir[e][2] + r * hn);
            float hnew = (1.0f - zz) * n + zz * h;

            h_reg[e] = hnew;
            __nv_bfloat16 hi = __float2bfloat16(hnew);
            __nv_bfloat16 lo = __float2bfloat16(hnew - __bfloat162float(hi));
            const int idx = b * Hn + j0 + gj;
            wAhi[idx] = hi;
            wAlo[idx] = lo;
            if (h0hi) {
                size_t o = (size_t)dir * SB * Hn + ((size_t)t * Bn + b) * Hn + j0 + gj;
                h0hi[o] = hi;
                h0lo[o] = lo;
            }
            if (out) {
                out[((size_t)b * Sn + t) * (2 * Hn) + (size_t)dir * Hn + j0 + gj] = hnew;
                if (t == Sn - 1)
                    out[(size_t)Bn * Sn * 2 * Hn + (size_t)b * 2 * Hn
                        + (size_t)dir * Hn + j0 + gj] = hnew;
            }
        }

        grid_barrier(dir);
    }
}

// ----------------------------------------------------------------------------
// Launcher
// ----------------------------------------------------------------------------
extern "C" void kernel_launch(void* const* d_in, const int* in_sizes, int n_in,
                              void* d_out, int out_size) {
    const float* x      = (const float*)d_in[0];
    const float* w_ih0f = (const float*)d_in[1];
    const float* w_hh0f = (const float*)d_in[2];
    const float* b_ih0f = (const float*)d_in[3];
    const float* b_hh0f = (const float*)d_in[4];
    const float* w_ih0b = (const float*)d_in[5];
    const float* w_hh0b = (const float*)d_in[6];
    const float* b_ih0b = (const float*)d_in[7];
    const float* b_hh0b = (const float*)d_in[8];
    const float* w_ih1f = (const float*)d_in[9];
    const float* w_hh1f = (const float*)d_in[10];
    const float* b_ih1f = (const float*)d_in[11];
    const float* b_hh1f = (const float*)d_in[12];
    const float* w_ih1b = (const float*)d_in[13];
    const float* w_hh1b = (const float*)d_in[14];
    const float* b_ih1b = (const float*)d_in[15];
    const float* b_hh1b = (const float*)d_in[16];
    float* out = (float*)d_out;

    float *gi, *bias0, *bias1;
    __nv_bfloat16 *xhi, *xlo, *h0hi, *h0lo, *hAhi, *hAlo;
    __nv_bfloat16 *wih0h, *wih0l, *whh0h, *whh0l, *wih1h, *wih1l, *whh1h, *whh1l;
    cudaGetSymbolAddress((void**)&xhi,   g_x_hi);
    cudaGetSymbolAddress((void**)&xlo,   g_x_lo);
    cudaGetSymbolAddress((void**)&gi,    g_gi);
    cudaGetSymbolAddress((void**)&h0hi,  g_h0_hi);
    cudaGetSymbolAddress((void**)&h0lo,  g_h0_lo);
    cudaGetSymbolAddress((void**)&hAhi,  g_hA_hi);
    cudaGetSymbolAddress((void**)&hAlo,  g_hA_lo);
    cudaGetSymbolAddress((void**)&bias0, g_bias0);
    cudaGetSymbolAddress((void**)&bias1, g_bias1);
    cudaGetSymbolAddress((void**)&wih0h, g_wih0_hi);
    cudaGetSymbolAddress((void**)&wih0l, g_wih0_lo);
    cudaGetSymbolAddress((void**)&whh0h, g_whh0_hi);
    cudaGetSymbolAddress((void**)&whh0l, g_whh0_lo);
    cudaGetSymbolAddress((void**)&wih1h, g_wih1_hi);
    cudaGetSymbolAddress((void**)&wih1l, g_wih1_lo);
    cudaGetSymbolAddress((void**)&whh1h, g_whh1_hi);
    cudaGetSymbolAddress((void**)&whh1l, g_whh1_lo);

    const int SMEM_RECUR = (2 * RB * 1024 + 4 * 2 * 64 * 32) * (int)sizeof(__nv_bfloat16);
    const int SMEM_GEMM  = (3 * 2 * 128 * 40 + 3 * 2 * 64 * 40) * (int)sizeof(__nv_bfloat16);
    static bool attr_done = false;
    if (!attr_done) {
        cudaFuncSetAttribute(k_recur, cudaFuncAttributeMaxDynamicSharedMemorySize, SMEM_RECUR);
        cudaFuncSetAttribute(k_gemm,  cudaFuncAttributeMaxDynamicSharedMemorySize, SMEM_GEMM);
        attr_done = true;
    }

    k_prep<<<dim3(2048, 9), 256>>>(
        w_ih0f, w_ih0b, w_ih1f, w_ih1b, w_hh0f, w_hh0b, w_hh1f, w_hh1b,
        b_ih0f, b_hh0f, b_ih0b, b_hh0b, b_ih1f, b_hh1f, b_ih1b, b_hh1b);
    k_xT_split<<<2048, 256>>>(x, xhi, xlo);

    // layer 0: batched input projection (x shared across dirs)
    k_gemm<<<dim3(G3 / 64, SB / 128, 2), 256, SMEM_GEMM>>>(
        xhi, xlo, 0,
        wih0h, wih0l, (size_t)G3 * INn,
        bias0, G3, gi, (size_t)SB * G3, G3, INn);

    // layer 0 recurrence
    k_recur<<<NRBLK, RTHREADS, SMEM_RECUR>>>(
        whh0h, whh0l, gi, hAhi, hAlo,
        b_hh0f, b_hh0b, h0hi, h0lo, nullptr);

    // layer 1: batched input projection (per-dir A)
    k_gemm<<<dim3(G3 / 64, SB / 128, 2), 256, SMEM_GEMM>>>(
        h0hi, h0lo, (size_t)SB * Hn,
        wih1h, wih1l, (size_t)G3 * Hn,
        bias1, G3, gi, (size_t)SB * G3, G3, Hn);

    // layer 1 recurrence (writes output)
    k_recur<<<NRBLK, RTHREADS, SMEM_RECUR>>>(
        whh1h, whh1l, gi, hAhi, hAlo,
        b_hh1f, b_hh1b, nullptr, nullptr, out);
}

// round 12
// speedup vs baseline: 1.5692x; 1.5692x over previous
#include <cuda_runtime.h>
#include <cuda_bf16.h>
#include <stdint.h>
#include <math.h>

// Problem constants
#define Bn  64
#define Sn  512
#define INn 512
#define Hn  1024
#define G3  3072          // 3*H
#define SB  32768         // S*B

#define NRBLK 128         // recurrence grid: 2 dirs x 64 tiles (16 j-cols, 48 W rows)
#define NBAR  64          // barrier domain: blocks per direction
#define RB    48
#define SWPAD 1032        // resident W smem row stride (bf16 elems)
#define RTHREADS 512

// ----------------------------------------------------------------------------
// Device scratch (static — no allocations allowed)
// ----------------------------------------------------------------------------
__device__ __nv_bfloat16 g_x_hi[(size_t)SB * INn];
__device__ __nv_bfloat16 g_x_lo[(size_t)SB * INn];
__device__ float g_gi[(size_t)2 * SB * G3];
__device__ __nv_bfloat16 g_h0_hi[(size_t)2 * SB * Hn];
__device__ __nv_bfloat16 g_h0_lo[(size_t)2 * SB * Hn];
__device__ float g_hcur[2 * Bn * Hn];
// hA double-buffered by step parity: [2 parity][2 dir][Bn][Hn]
__device__ __nv_bfloat16 g_hA_hi[2 * 2 * Bn * Hn];
__device__ __nv_bfloat16 g_hA_lo[2 * 2 * Bn * Hn];
__device__ float g_bias0[2 * G3];
__device__ float g_bias1[2 * G3];

__device__ __nv_bfloat16 g_wih0_hi[(size_t)2 * G3 * INn];
__device__ __nv_bfloat16 g_wih0_lo[(size_t)2 * G3 * INn];
__device__ __nv_bfloat16 g_wih1_hi[(size_t)2 * G3 * Hn];
__device__ __nv_bfloat16 g_wih1_lo[(size_t)2 * G3 * Hn];
// W_hh stored ROW-PERMUTED: row p = tile*48 + gate*16 + jj  <-  src row gate*H + tile*16 + jj
__device__ __nv_bfloat16 g_whh0_hi[(size_t)2 * G3 * Hn];
__device__ __nv_bfloat16 g_whh0_lo[(size_t)2 * G3 * Hn];
__device__ __nv_bfloat16 g_whh1_hi[(size_t)2 * G3 * Hn];
__device__ __nv_bfloat16 g_whh1_lo[(size_t)2 * G3 * Hn];

// per-direction barrier state
__device__ volatile unsigned g_bar_gen[2];
__device__ unsigned g_bar_cnt[2];

// ----------------------------------------------------------------------------
// cp.async / ldmatrix helpers
// ----------------------------------------------------------------------------
__device__ __forceinline__ void cp16(void* dst, const void* src) {
    uint32_t d = (uint32_t)__cvta_generic_to_shared(dst);
    asm volatile("cp.async.cg.shared.global [%0], [%1], 16;\n" :: "r"(d), "l"(src));
}
#define CP_COMMIT() asm volatile("cp.async.commit_group;\n")
#define CP_WAIT0()  asm volatile("cp.async.wait_group 0;\n")
#define CP_WAIT1()  asm volatile("cp.async.wait_group 1;\n")

__device__ __forceinline__ void ldsm4(uint32_t r[4], uint32_t saddr) {
    asm volatile("ldmatrix.sync.aligned.m8n8.x4.shared.b16 {%0,%1,%2,%3}, [%4];"
                 : "=r"(r[0]), "=r"(r[1]), "=r"(r[2]), "=r"(r[3]) : "r"(saddr));
}
__device__ __forceinline__ void ldsm2(uint32_t r[2], uint32_t saddr) {
    asm volatile("ldmatrix.sync.aligned.m8n8.x2.shared.b16 {%0,%1}, [%2];"
                 : "=r"(r[0]), "=r"(r[1]) : "r"(saddr));
}

__device__ __forceinline__ void mma_bf16(float c[4], const uint32_t a[4],
                                         uint32_t b0, uint32_t b1) {
    asm("mma.sync.aligned.m16n8k16.row.col.f32.bf16.bf16.f32 "
        "{%0,%1,%2,%3}, {%4,%5,%6,%7}, {%8,%9}, {%0,%1,%2,%3};\n"
        : "+f"(c[0]), "+f"(c[1]), "+f"(c[2]), "+f"(c[3])
        : "r"(a[0]), "r"(a[1]), "r"(a[2]), "r"(a[3]), "r"(b0), "r"(b1));
}

__device__ __forceinline__ float fsigmoid(float x) {
    return 1.0f / (1.0f + __expf(-x));
}

__device__ __forceinline__ uint32_t smem_u32(const void* p) {
    return (uint32_t)__cvta_generic_to_shared(p);
}

// ----------------------------------------------------------------------------
// Prep: all weight splits (+ W_hh permutation) + biases, one kernel
// ----------------------------------------------------------------------------
__device__ __forceinline__ void split_at(const float* src, size_t si,
                                         __nv_bfloat16* hi, __nv_bfloat16* lo, size_t di) {
    float v = src[si];
    __nv_bfloat16 h = __float2bfloat16(v);
    hi[di] = h;
    lo[di] = __float2bfloat16(v - __bfloat162float(h));
}

__global__ void k_prep(
    const float* __restrict__ wih0f, const float* __restrict__ wih0b,
    const float* __restrict__ wih1f, const float* __restrict__ wih1b,
    const float* __restrict__ whh0f, const float* __restrict__ whh0b,
    const float* __restrict__ whh1f, const float* __restrict__ whh1b,
    const float* __restrict__ bih0f, const float* __restrict__ bhh0f,
    const float* __restrict__ bih0b, const float* __restrict__ bhh0b,
    const float* __restrict__ bih1f, const float* __restrict__ bhh1f,
    const float* __restrict__ bih1b, const float* __restrict__ bhh1b)
{
    const int seg = blockIdx.y;
    const int stride = gridDim.x * blockDim.x;
    int i0 = blockIdx.x * blockDim.x + threadIdx.x;

    if (seg == 0) {
        for (int i = i0; i < G3 * INn; i += stride)
            split_at(wih0f, i, g_wih0_hi, g_wih0_lo, i);
    } else if (seg == 1) {
        for (int i = i0; i < G3 * INn; i += stride) {
            int n = i / INn, k = i % INn;
            split_at(wih0b, (size_t)n * INn + (INn - 1 - k),
                     g_wih0_hi, g_wih0_lo, (size_t)G3 * INn + i);
        }
    } else if (seg == 2) {
        for (int i = i0; i < G3 * Hn; i += stride)
            split_at(wih1f, i, g_wih1_hi, g_wih1_lo, i);
    } else if (seg == 3) {
        for (int i = i0; i < G3 * Hn; i += stride)
            split_at(wih1b, i, g_wih1_hi, g_wih1_lo, (size_t)G3 * Hn + i);
    } else if (seg <= 7) {
        const float* src = (seg == 4) ? whh0f : (seg == 5) ? whh0b
                         : (seg == 6) ? whh1f : whh1b;
        __nv_bfloat16* hi = (seg <= 5) ? g_whh0_hi : g_whh1_hi;
        __nv_bfloat16* lo = (seg <= 5) ? g_whh0_lo : g_whh1_lo;
        size_t doff = (seg == 5 || seg == 7) ? (size_t)G3 * Hn : 0;
        for (int i = i0; i < G3 * Hn; i += stride) {
            int prow = i >> 10, k = i & 1023;
            int tile = prow / 48, gate = (prow % 48) >> 4, jj = prow & 15;
            size_t srow = (size_t)gate * Hn + tile * 16 + jj;
            split_at(src, srow * Hn + k, hi, lo, doff + i);
        }
    } else {
        for (int i = i0; i < G3; i += stride) {
            float add = (i < 2 * Hn) ? 1.0f : 0.0f;
            g_bias0[i]      = bih0f[i] + add * bhh0f[i];
            g_bias0[G3 + i] = bih0b[i] + add * bhh0b[i];
            g_bias1[i]      = bih1f[i] + add * bhh1f[i];
            g_bias1[G3 + i] = bih1b[i] + add * bhh1b[i];
        }
    }
}

__global__ void k_xT_split(const float* __restrict__ x,
                           __nv_bfloat16* __restrict__ hi,
                           __nv_bfloat16* __restrict__ lo) {
    size_t total = (size_t)Bn * Sn * INn;
    for (size_t i = (size_t)blockIdx.x * blockDim.x + threadIdx.x; i < total;
         i += (size_t)gridDim.x * blockDim.x) {
        int k = (int)(i % INn);
        size_t tmp = i / INn;
        int s = (int)(tmp % Sn);
        int b = (int)(tmp / Sn);
        float v = x[i];
        __nv_bfloat16 h = __float2bfloat16(v);
        size_t o = ((size_t)s * Bn + b) * INn + k;
        hi[o] = h;
        lo[o] = __float2bfloat16(v - __bfloat162float(h));
    }
}

// ----------------------------------------------------------------------------
// Batched split-bf16 GEMM, 128x128 tile, 512 threads (16 warps, 4M x 4N),
// warp tile 32x32, 3-stage cp.async, ldmatrix fragments.
// C[M,N] = A[M,K] * W[N,K]^T (+bias). Inner loop identical to proven R6 kernel.
// ----------------------------------------------------------------------------
__global__ __launch_bounds__(512) void k_gemm(
    const __nv_bfloat16* __restrict__ Ahi, const __nv_bfloat16* __restrict__ Alo,
    size_t aStrZ,
    const __nv_bfloat16* __restrict__ Whi, const __nv_bfloat16* __restrict__ Wlo,
    size_t wStrZ,
    const float* __restrict__ bias, size_t bStrZ,
    float* __restrict__ C, size_t cStrZ,
    int N, int K)
{
    const int z = blockIdx.z;
    Ahi += (size_t)z * aStrZ;  Alo += (size_t)z * aStrZ;
    Whi += (size_t)z * wStrZ;  Wlo += (size_t)z * wStrZ;
    const float* biasz = bias ? (bias + (size_t)z * bStrZ) : nullptr;
    C += (size_t)z * cStrZ;

    const int m0 = blockIdx.y * 128;
    const int n0 = blockIdx.x * 128;

    extern __shared__ __align__(16) __nv_bfloat16 sm[];
    __nv_bfloat16* sA = sm;                     // [3][2][128][40]
    __nv_bfloat16* sW = sm + 3 * 2 * 128 * 40;  // [3][2][128][40]
    const uint32_t sAaddr = smem_u32(sA);
    const uint32_t sWaddr = smem_u32(sW);

    const int tid  = threadIdx.x;
    const int lane = tid & 31;
    const int warp = tid >> 5;
    const int wm = warp & 3;      // 32 M rows (2 subtiles of 16)
    const int wn = warp >> 2;     // 32 N cols (4 nf of 8)
    const int g  = lane >> 2;
    const int tq = lane & 3;

    // copy mapping: 512 threads, 1 cp16 per plane per matrix per chunk
    const int crow = tid >> 2;          // 0..127
    const int ccol = (tid & 3) * 8;
    const int lrow  = lane & 15;
    const int lcol8 = (lane >> 4) * 8;

    float acc[2][4][4];
#pragma unroll
    for (int a = 0; a < 2; a++)
#pragma unroll
        for (int b = 0; b < 4; b++)
#pragma unroll
            for (int c = 0; c < 4; c++) acc[a][b][c] = 0.0f;

    const int nk = K / 32;

    auto copy_chunk = [&](int ci, int st) {
        const int k0 = ci * 32;
        const size_t ao = (size_t)(m0 + crow) * K + k0 + ccol;
        cp16(sA + ((st * 2 + 0) * 128 + crow) * 40 + ccol, Ahi + ao);
        cp16(sA + ((st * 2 + 1) * 128 + crow) * 40 + ccol, Alo + ao);
        const size_t wo = (size_t)(n0 + crow) * K + k0 + ccol;
        cp16(sW + ((st * 2 + 0) * 128 + crow) * 40 + ccol, Whi + wo);
        cp16(sW + ((st * 2 + 1) * 128 + crow) * 40 + ccol, Wlo + wo);
        CP_COMMIT();
    };

    copy_chunk(0, 0);
    copy_chunk(1, 1);

    for (int ci = 0; ci < nk; ci++) {
        const int st = ci % 3;
        CP_WAIT1();
        __syncthreads();
        if (ci + 2 < nk) copy_chunk(ci + 2, (ci + 2) % 3);
        else CP_COMMIT();

#pragma unroll
        for (int kk = 0; kk < 32; kk += 16) {
            uint32_t ah[2][4], al[2][4];
#pragma unroll
            for (int ms = 0; ms < 2; ms++) {
                uint32_t base = ((st * 2 + 0) * 128 + wm * 32 + ms * 16 + lrow) * 40
                                + kk + lcol8;
                ldsm4(ah[ms], sAaddr + base * 2);
                base = ((st * 2 + 1) * 128 + wm * 32 + ms * 16 + lrow) * 40 + kk + lcol8;
                ldsm4(al[ms], sAaddr + base * 2);
            }
            uint32_t bh01[4], bl01[4], bh23[4], bl23[4];
            {
                uint32_t b = ((st * 2 + 0) * 128 + wn * 32 + lrow) * 40 + kk + lcol8;
                ldsm4(bh01, sWaddr + b * 2);
                b = ((st * 2 + 1) * 128 + wn * 32 + lrow) * 40 + kk + lcol8;
                ldsm4(bl01, sWaddr + b * 2);
                b = ((st * 2 + 0) * 128 + wn * 32 + 16 + lrow) * 40 + kk + lcol8;
                ldsm4(bh23, sWaddr + b * 2);
                b = ((st * 2 + 1) * 128 + wn * 32 + 16 + lrow) * 40 + kk + lcol8;
                ldsm4(bl23, sWaddr + b * 2);
            }
#pragma unroll
            for (int ms = 0; ms < 2; ms++) {
                mma_bf16(acc[ms][0], ah[ms], bh01[0], bh01[2]);
                mma_bf16(acc[ms][0], ah[ms], bl01[0], bl01[2]);
                mma_bf16(acc[ms][0], al[ms], bh01[0], bh01[2]);
                mma_bf16(acc[ms][1], ah[ms], bh01[1], bh01[3]);
                mma_bf16(acc[ms][1], ah[ms], bl01[1], bl01[3]);
                mma_bf16(acc[ms][1], al[ms], bh01[1], bh01[3]);
                mma_bf16(acc[ms][2], ah[ms], bh23[0], bh23[2]);
                mma_bf16(acc[ms][2], ah[ms], bl23[0], bl23[2]);
                mma_bf16(acc[ms][2], al[ms], bh23[0], bh23[2]);
                mma_bf16(acc[ms][3], ah[ms], bh23[1], bh23[3]);
                mma_bf16(acc[ms][3], ah[ms], bl23[1], bl23[3]);
                mma_bf16(acc[ms][3], al[ms], bh23[1], bh23[3]);
            }
        }
    }

#pragma unroll
    for (int ms = 0; ms < 2; ms++)
#pragma unroll
        for (int nf = 0; nf < 4; nf++) {
            int col = n0 + wn * 32 + nf * 8 + tq * 2;
            float b0 = biasz ? biasz[col]     : 0.0f;
            float b1 = biasz ? biasz[col + 1] : 0.0f;
            int row = m0 + wm * 32 + ms * 16 + g;
            float* c0 = C + (size_t)row * N + col;
            c0[0] = acc[ms][nf][0] + b0;
            c0[1] = acc[ms][nf][1] + b1;
            float* c1 = C + (size_t)(row + 8) * N + col;
            c1[0] = acc[ms][nf][2] + b0;
            c1[1] = acc[ms][nf][3] + b1;
        }
}

// ----------------------------------------------------------------------------
// Per-direction grid barrier (64 blocks per domain)
// ----------------------------------------------------------------------------
__device__ __forceinline__ void grid_barrier(int dir) {
    __syncthreads();
    if (threadIdx.x == 0) {
        unsigned gen = g_bar_gen[dir];
        __threadfence();
        if (atomicAdd(&g_bar_cnt[dir], 1) == NBAR - 1) {
            g_bar_cnt[dir] = 0;
            __threadfence();
            g_bar_gen[dir] = gen + 1;
        } else {
            while (g_bar_gen[dir] == gen) { __nanosleep(32); }
        }
        __threadfence();
    }
    __syncthreads();
}

// ----------------------------------------------------------------------------
// Gate-fused persistent recurrence (R6 structure, proven), 512 threads.
// Warps: wk(2 k16-slices per 32-chunk) x wm(4x16 rows) x wn(2x24 cols).
// 3-stage cp.async A ring, padded smem (SWPAD), one grid barrier per step.
// hA double-buffered by step parity (race fix).
// ----------------------------------------------------------------------------
__global__ __launch_bounds__(RTHREADS) void k_recur(
    const __nv_bfloat16* __restrict__ Whi,  // [2][G3][Hn] permuted rows
    const __nv_bfloat16* __restrict__ Wlo,
    const float* __restrict__ gi,           // [2][SB][G3]
    float* __restrict__ hcur,               // [2][B][H]
    __nv_bfloat16* __restrict__ hAhi,       // [2 par][2 dir][B][H]
    __nv_bfloat16* __restrict__ hAlo,
    const float* __restrict__ bhh_f, const float* __restrict__ bhh_b,
    __nv_bfloat16* __restrict__ h0hi,       // layer0: [2][SB][H]; else null
    __nv_bfloat16* __restrict__ h0lo,
    float* __restrict__ out)                // layer1: output; else null
{
    extern __shared__ __align__(16) char sm_raw[];
    __nv_bfloat16* sWhi = reinterpret_cast<__nv_bfloat16*>(sm_raw);
    __nv_bfloat16* sWlo = sWhi + RB * SWPAD;
    __nv_bfloat16* sAb  = sWlo + RB * SWPAD;           // [3][2][64][40]
    float* sC = reinterpret_cast<float*>(sAb);          // alias, [2][64][49]
    const uint32_t sAaddr  = smem_u32(sAb);
    const uint32_t sWhaddr = smem_u32(sWhi);
    const uint32_t sWladdr = smem_u32(sWlo);

    const int tid  = threadIdx.x;
    const int dir  = blockIdx.x >> 6;
    const int tile = blockIdx.x & 63;
    const int j0   = tile * 16;
    const int p0   = tile * RB;
    const int HAS  = 2 * Bn * Hn;

    const __nv_bfloat16* WhiD = Whi + (size_t)dir * G3 * Hn;
    const __nv_bfloat16* WloD = Wlo + (size_t)dir * G3 * Hn;
    const float* bhh = dir ? bhh_b : bhh_f;

    const int lane = tid & 31;
    const int warp = tid >> 5;
    const int wk = warp >> 3;        // k16 slice within 32-chunk
    const int w8 = warp & 7;
    const int wm = w8 & 3;           // 16 M rows
    const int wn = w8 >> 2;          // 24 W cols
    const int kk = wk * 16;
    const int lrow   = lane & 15;
    const int lcol8  = (lane >> 4) * 8;
    const int lrow2  = lane & 7;
    const int lcol82 = ((lane >> 3) & 1) * 8;
    const int g  = lane >> 2;
    const int tq = lane & 3;

    // A-copy mapping: 512 threads -> one cp16 per 32-chunk
    const int cp_p   = tid >> 8;
    const int cp_row = (tid >> 2) & 63;
    const int cp_q   = tid & 3;

    // gate-phase mapping
    const int gj = tid & 15;
    const int gb = tid >> 4;
    const float bias_n = bhh[2 * Hn + j0 + gj];

    // ---- load resident W slice ----
    for (int i = tid; i < RB * (Hn / 8); i += RTHREADS) {
        int row = i >> 7;
        int q   = i & 127;
        const size_t off = (size_t)(p0 + row) * Hn + q * 8;
        cp16(&sWhi[row * SWPAD + q * 8], WhiD + off);
        cp16(&sWlo[row * SWPAD + q * 8], WloD + off);
    }
    CP_COMMIT();

    // ---- zero own state (both parities) ----
    for (int i = tid; i < Bn * 16; i += RTHREADS) {
        int b = i >> 4, j = i & 15;
        int idx = dir * (Bn * Hn) + b * Hn + j0 + j;
        hcur[idx] = 0.0f;
        hAhi[idx] = __float2bfloat16(0.0f);
        hAlo[idx] = __float2bfloat16(0.0f);
        hAhi[HAS + idx] = __float2bfloat16(0.0f);
        hAlo[HAS + idx] = __float2bfloat16(0.0f);
    }
    CP_WAIT0();
    grid_barrier(dir);

    const __nv_bfloat16* pAhi = nullptr;
    const __nv_bfloat16* pAlo = nullptr;

    auto copyA = [&](int ci, int st) {
        const __nv_bfloat16* src = cp_p ? pAlo : pAhi;
        cp16(&sAb[((st * 2 + cp_p) * 64 + cp_row) * 40 + cp_q * 8],
             src + (size_t)cp_row * Hn + ci * 32 + cp_q * 8);
        CP_COMMIT();
    };

    for (int t = 0; t < Sn; ++t) {
        const int par_r = t & 1;
        const int par_w = par_r ^ 1;
        pAhi = hAhi + (size_t)par_r * HAS + (size_t)dir * Bn * Hn;
        pAlo = hAlo + (size_t)par_r * HAS + (size_t)dir * Bn * Hn;

        float acc[3][4];
#pragma unroll
        for (int i = 0; i < 3; i++)
#pragma unroll
            for (int j = 0; j < 4; j++) acc[i][j] = 0.0f;

        copyA(0, 0);
        copyA(1, 1);

        for (int ci = 0; ci < 32; ci++) {
            const int st = ci % 3;
            CP_WAIT1();
            __syncthreads();
            if (ci + 2 < 32) copyA(ci + 2, (ci + 2) % 3);
            else CP_COMMIT();

            const int kg = ci * 32 + kk;
            uint32_t ah[4], al[4];
            ldsm4(ah, sAaddr + (((st * 2 + 0) * 64 + wm * 16 + lrow) * 40 + kk + lcol8) * 2);
            ldsm4(al, sAaddr + (((st * 2 + 1) * 64 + wm * 16 + lrow) * 40 + kk + lcol8) * 2);
            uint32_t bh01[4], bl01[4], bh2[2], bl2[2];
            ldsm4(bh01, sWhaddr + ((wn * 24 + lrow) * SWPAD + kg + lcol8) * 2);
            ldsm4(bl01, sWladdr + ((wn * 24 + lrow) * SWPAD + kg + lcol8) * 2);
            ldsm2(bh2,  sWhaddr + ((wn * 24 + 16 + lrow2) * SWPAD + kg + lcol82) * 2);
            ldsm2(bl2,  sWladdr + ((wn * 24 + 16 + lrow2) * SWPAD + kg + lcol82) * 2);

            mma_bf16(acc[0], ah, bh01[0], bh01[2]);
            mma_bf16(acc[0], ah, bl01[0], bl01[2]);
            mma_bf16(acc[0], al, bh01[0], bh01[2]);
            mma_bf16(acc[1], ah, bh01[1], bh01[3]);
            mma_bf16(acc[1], ah, bl01[1], bl01[3]);
            mma_bf16(acc[1], al, bh01[1], bh01[3]);
            mma_bf16(acc[2], ah, bh2[0], bh2[1]);
            mma_bf16(acc[2], ah, bl2[0], bl2[1]);
            mma_bf16(acc[2], al, bh2[0], bh2[1]);
        }

        // ---- epilogue: wk partials -> sC0/sC1 (alias A ring) ----
        __syncthreads();
        float* sC0 = sC;
        float* sC1 = sC + 64 * 49;
        {
            float* d = wk ? sC1 : sC0;
#pragma unroll
            for (int nf = 0; nf < 3; nf++) {
                int col = wn * 24 + nf * 8 + tq * 2;
                int row = wm * 16 + g;
                d[row * 49 + col]           = acc[nf][0];
                d[row * 49 + col + 1]       = acc[nf][1];
                d[(row + 8) * 49 + col]     = acc[nf][2];
                d[(row + 8) * 49 + col + 1] = acc[nf][3];
            }
        }
        __syncthreads();

        // ---- gate update for own (dir, all b, j0+gj) ----
        const float* giT = gi + (size_t)dir * SB * G3 + (size_t)t * Bn * G3;
        __nv_bfloat16* wAhi = hAhi + (size_t)par_w * HAS + (size_t)dir * Bn * Hn;
        __nv_bfloat16* wAlo = hAlo + (size_t)par_w * HAS + (size_t)dir * Bn * Hn;
#pragma unroll
        for (int e = 0; e < 2; e++) {
            const int b = gb + e * 32;
            const float* gib = giT + (size_t)b * G3;
            const float* c0 = sC0 + b * 49;
            const float* c1 = sC1 + b * 49;
            float ir  = gib[j0 + gj];
            float iz  = gib[Hn + j0 + gj];
            float inn = gib[2 * Hn + j0 + gj];
            float hr  = c0[gj]      + c1[gj];
            float hz  = c0[16 + gj] + c1[16 + gj];
            float hn  = c0[32 + gj] + c1[32 + gj] + bias_n;
            const int idx = dir * (Bn * Hn) + b * Hn + j0 + gj;
            float h = hcur[idx];

            float r  = fsigmoid(ir + hr);
            float zz = fsigmoid(iz + hz);
            float n  = tanhf(inn + r * hn);
            float hnew = (1.0f - zz) * n + zz * h;

            hcur[idx] = hnew;
            __nv_bfloat16 hi = __float2bfloat16(hnew);
            __nv_bfloat16 lo = __float2bfloat16(hnew - __bfloat162float(hi));
            const int widx = b * Hn + j0 + gj;
            wAhi[widx] = hi;
            wAlo[widx] = lo;
            if (h0hi) {
                size_t o = (size_t)dir * SB * Hn + ((size_t)t * Bn + b) * Hn + j0 + gj;
                h0hi[o] = hi;
                h0lo[o] = lo;
            }
            if (out) {
                out[((size_t)b * Sn + t) * (2 * Hn) + (size_t)dir * Hn + j0 + gj] = hnew;
                if (t == Sn - 1)
                    out[(size_t)Bn * Sn * 2 * Hn + (size_t)b * 2 * Hn
                        + (size_t)dir * Hn + j0 + gj] = hnew;
            }
        }

        grid_barrier(dir);
    }
}

// ----------------------------------------------------------------------------
// Launcher
// ----------------------------------------------------------------------------
extern "C" void kernel_launch(void* const* d_in, const int* in_sizes, int n_in,
                              void* d_out, int out_size) {
    const float* x      = (const float*)d_in[0];
    const float* w_ih0f = (const float*)d_in[1];
    const float* w_hh0f = (const float*)d_in[2];
    const float* b_ih0f = (const float*)d_in[3];
    const float* b_hh0f = (const float*)d_in[4];
    const float* w_ih0b = (const float*)d_in[5];
    const float* w_hh0b = (const float*)d_in[6];
    const float* b_ih0b = (const float*)d_in[7];
    const float* b_hh0b = (const float*)d_in[8];
    const float* w_ih1f = (const float*)d_in[9];
    const float* w_hh1f = (const float*)d_in[10];
    const float* b_ih1f = (const float*)d_in[11];
    const float* b_hh1f = (const float*)d_in[12];
    const float* w_ih1b = (const float*)d_in[13];
    const float* w_hh1b = (const float*)d_in[14];
    const float* b_ih1b = (const float*)d_in[15];
    const float* b_hh1b = (const float*)d_in[16];
    float* out = (float*)d_out;

    float *gi, *hcur, *bias0, *bias1;
    __nv_bfloat16 *xhi, *xlo, *h0hi, *h0lo, *hAhi, *hAlo;
    __nv_bfloat16 *wih0h, *wih0l, *whh0h, *whh0l, *wih1h, *wih1l, *whh1h, *whh1l;
    cudaGetSymbolAddress((void**)&xhi,   g_x_hi);
    cudaGetSymbolAddress((void**)&xlo,   g_x_lo);
    cudaGetSymbolAddress((void**)&gi,    g_gi);
    cudaGetSymbolAddress((void**)&h0hi,  g_h0_hi);
    cudaGetSymbolAddress((void**)&h0lo,  g_h0_lo);
    cudaGetSymbolAddress((void**)&hcur,  g_hcur);
    cudaGetSymbolAddress((void**)&hAhi,  g_hA_hi);
    cudaGetSymbolAddress((void**)&hAlo,  g_hA_lo);
    cudaGetSymbolAddress((void**)&bias0, g_bias0);
    cudaGetSymbolAddress((void**)&bias1, g_bias1);
    cudaGetSymbolAddress((void**)&wih0h, g_wih0_hi);
    cudaGetSymbolAddress((void**)&wih0l, g_wih0_lo);
    cudaGetSymbolAddress((void**)&whh0h, g_whh0_hi);
    cudaGetSymbolAddress((void**)&whh0l, g_whh0_lo);
    cudaGetSymbolAddress((void**)&wih1h, g_wih1_hi);
    cudaGetSymbolAddress((void**)&wih1l, g_wih1_lo);
    cudaGetSymbolAddress((void**)&whh1h, g_whh1_hi);
    cudaGetSymbolAddress((void**)&whh1l, g_whh1_lo);

    const int SMEM_RECUR = (2 * RB * SWPAD + 3 * 2 * 64 * 40) * (int)sizeof(__nv_bfloat16);
    const int SMEM_GEMM  = (3 * 2 * 128 * 40 * 2) * (int)sizeof(__nv_bfloat16); // 122,880
    static bool attr_done = false;
    if (!attr_done) {
        cudaFuncSetAttribute(k_recur, cudaFuncAttributeMaxDynamicSharedMemorySize, SMEM_RECUR);
        cudaFuncSetAttribute(k_gemm,  cudaFuncAttributeMaxDynamicSharedMemorySize, SMEM_GEMM);
        attr_done = true;
    }

    k_prep<<<dim3(2048, 9), 256>>>(
        w_ih0f, w_ih0b, w_ih1f, w_ih1b, w_hh0f, w_hh0b, w_hh1f, w_hh1b,
        b_ih0f, b_hh0f, b_ih0b, b_hh0b, b_ih1f, b_hh1f, b_ih1b, b_hh1b);
    k_xT_split<<<2048, 256>>>(x, xhi, xlo);

    // layer 0: batched input projection (x shared across dirs)
    k_gemm<<<dim3(G3 / 128, SB / 128, 2), 512, SMEM_GEMM>>>(
        xhi, xlo, 0,
        wih0h, wih0l, (size_t)G3 * INn,
        bias0, G3, gi, (size_t)SB * G3, G3, INn);

    // layer 0 recurrence
    k_recur<<<NRBLK, RTHREADS, SMEM_RECUR>>>(
        whh0h, whh0l, gi, hcur, hAhi, hAlo,
        b_hh0f, b_hh0b, h0hi, h0lo, nullptr);

    // layer 1: batched input projection (per-dir A)
    k_gemm<<<dim3(G3 / 128, SB / 128, 2), 512, SMEM_GEMM>>>(
        h0hi, h0lo, (size_t)SB * Hn,
        wih1h, wih1l, (size_t)G3 * Hn,
        bias1, G3, gi, (size_t)SB * G3, G3, Hn);

    // layer 1 recurrence (writes output)
    k_recur<<<NRBLK, RTHREADS, SMEM_RECUR>>>(
        whh1h, whh1l, gi, hcur, hAhi, hAlo,
        b_hh1f, b_hh1b, nullptr, nullptr, out);
}

// round 13
// speedup vs baseline: 1.8109x; 1.1541x over previous
#include <cuda_runtime.h>
#include <cuda_bf16.h>
#include <stdint.h>
#include <math.h>

// Problem constants
#define Bn  64
#define Sn  512
#define INn 512
#define Hn  1024
#define G3  3072          // 3*H
#define SB  32768         // S*B

#define NRBLK 128         // recurrence grid: 2 dirs x 64 tiles (16 j-cols, 48 W rows)
#define NBAR  64          // barrier domain: blocks per direction
#define RB    48
#define SWPAD 1032        // resident W smem row stride (bf16 elems)
#define RTHREADS 512

// ----------------------------------------------------------------------------
// Device scratch (static — no allocations allowed)
// ----------------------------------------------------------------------------
__device__ __nv_bfloat16 g_x_hi[(size_t)SB * INn];
__device__ __nv_bfloat16 g_x_lo[(size_t)SB * INn];
__device__ float g_gi[(size_t)2 * SB * G3];
__device__ __nv_bfloat16 g_h0_hi[(size_t)2 * SB * Hn];
__device__ __nv_bfloat16 g_h0_lo[(size_t)2 * SB * Hn];
// hA double-buffered by step parity: [2 parity][2 dir][Bn][Hn]
__device__ __nv_bfloat16 g_hA_hi[2 * 2 * Bn * Hn];
__device__ __nv_bfloat16 g_hA_lo[2 * 2 * Bn * Hn];
__device__ float g_bias0[2 * G3];
__device__ float g_bias1[2 * G3];

__device__ __nv_bfloat16 g_wih0_hi[(size_t)2 * G3 * INn];
__device__ __nv_bfloat16 g_wih0_lo[(size_t)2 * G3 * INn];
__device__ __nv_bfloat16 g_wih1_hi[(size_t)2 * G3 * Hn];
__device__ __nv_bfloat16 g_wih1_lo[(size_t)2 * G3 * Hn];
// W_hh stored ROW-PERMUTED: row p = tile*48 + gate*16 + jj  <-  src row gate*H + tile*16 + jj
__device__ __nv_bfloat16 g_whh0_hi[(size_t)2 * G3 * Hn];
__device__ __nv_bfloat16 g_whh0_lo[(size_t)2 * G3 * Hn];
__device__ __nv_bfloat16 g_whh1_hi[(size_t)2 * G3 * Hn];
__device__ __nv_bfloat16 g_whh1_lo[(size_t)2 * G3 * Hn];

// per-direction barrier counters (monotonic within a replay; reset in k_prep)
__device__ unsigned g_bar_ctr[2];

// ----------------------------------------------------------------------------
// cp.async / ldmatrix helpers
// ----------------------------------------------------------------------------
__device__ __forceinline__ void cp16(void* dst, const void* src) {
    uint32_t d = (uint32_t)__cvta_generic_to_shared(dst);
    asm volatile("cp.async.cg.shared.global [%0], [%1], 16;\n" :: "r"(d), "l"(src));
}
#define CP_COMMIT() asm volatile("cp.async.commit_group;\n")
#define CP_WAIT0()  asm volatile("cp.async.wait_group 0;\n")
#define CP_WAIT1()  asm volatile("cp.async.wait_group 1;\n")

__device__ __forceinline__ void ldsm4(uint32_t r[4], uint32_t saddr) {
    asm volatile("ldmatrix.sync.aligned.m8n8.x4.shared.b16 {%0,%1,%2,%3}, [%4];"
                 : "=r"(r[0]), "=r"(r[1]), "=r"(r[2]), "=r"(r[3]) : "r"(saddr));
}
__device__ __forceinline__ void ldsm2(uint32_t r[2], uint32_t saddr) {
    asm volatile("ldmatrix.sync.aligned.m8n8.x2.shared.b16 {%0,%1}, [%2];"
                 : "=r"(r[0]), "=r"(r[1]) : "r"(saddr));
}

__device__ __forceinline__ void mma_bf16(float c[4], const uint32_t a[4],
                                         uint32_t b0, uint32_t b1) {
    asm("mma.sync.aligned.m16n8k16.row.col.f32.bf16.bf16.f32 "
        "{%0,%1,%2,%3}, {%4,%5,%6,%7}, {%8,%9}, {%0,%1,%2,%3};\n"
        : "+f"(c[0]), "+f"(c[1]), "+f"(c[2]), "+f"(c[3])
        : "r"(a[0]), "r"(a[1]), "r"(a[2]), "r"(a[3]), "r"(b0), "r"(b1));
}

__device__ __forceinline__ float fsigmoid(float x) {
    return 1.0f / (1.0f + __expf(-x));
}

__device__ __forceinline__ uint32_t smem_u32(const void* p) {
    return (uint32_t)__cvta_generic_to_shared(p);
}

// ----------------------------------------------------------------------------
// Prep: all weight splits (+ W_hh permutation) + biases + barrier reset
// ----------------------------------------------------------------------------
__device__ __forceinline__ void split_at(const float* src, size_t si,
                                         __nv_bfloat16* hi, __nv_bfloat16* lo, size_t di) {
    float v = src[si];
    __nv_bfloat16 h = __float2bfloat16(v);
    hi[di] = h;
    lo[di] = __float2bfloat16(v - __bfloat162float(h));
}

__global__ void k_prep(
    const float* __restrict__ wih0f, const float* __restrict__ wih0b,
    const float* __restrict__ wih1f, const float* __restrict__ wih1b,
    const float* __restrict__ whh0f, const float* __restrict__ whh0b,
    const float* __restrict__ whh1f, const float* __restrict__ whh1b,
    const float* __restrict__ bih0f, const float* __restrict__ bhh0f,
    const float* __restrict__ bih0b, const float* __restrict__ bhh0b,
    const float* __restrict__ bih1f, const float* __restrict__ bhh1f,
    const float* __restrict__ bih1b, const float* __restrict__ bhh1b)
{
    const int seg = blockIdx.y;
    const int stride = gridDim.x * blockDim.x;
    int i0 = blockIdx.x * blockDim.x + threadIdx.x;

    if (seg == 0) {
        for (int i = i0; i < G3 * INn; i += stride)
            split_at(wih0f, i, g_wih0_hi, g_wih0_lo, i);
    } else if (seg == 1) {
        for (int i = i0; i < G3 * INn; i += stride) {
            int n = i / INn, k = i % INn;
            split_at(wih0b, (size_t)n * INn + (INn - 1 - k),
                     g_wih0_hi, g_wih0_lo, (size_t)G3 * INn + i);
        }
    } else if (seg == 2) {
        for (int i = i0; i < G3 * Hn; i += stride)
            split_at(wih1f, i, g_wih1_hi, g_wih1_lo, i);
    } else if (seg == 3) {
        for (int i = i0; i < G3 * Hn; i += stride)
            split_at(wih1b, i, g_wih1_hi, g_wih1_lo, (size_t)G3 * Hn + i);
    } else if (seg <= 7) {
        const float* src = (seg == 4) ? whh0f : (seg == 5) ? whh0b
                         : (seg == 6) ? whh1f : whh1b;
        __nv_bfloat16* hi = (seg <= 5) ? g_whh0_hi : g_whh1_hi;
        __nv_bfloat16* lo = (seg <= 5) ? g_whh0_lo : g_whh1_lo;
        size_t doff = (seg == 5 || seg == 7) ? (size_t)G3 * Hn : 0;
        for (int i = i0; i < G3 * Hn; i += stride) {
            int prow = i >> 10, k = i & 1023;
            int tile = prow / 48, gate = (prow % 48) >> 4, jj = prow & 15;
            size_t srow = (size_t)gate * Hn + tile * 16 + jj;
            split_at(src, srow * Hn + k, hi, lo, doff + i);
        }
    } else {
        if (blockIdx.x == 0 && threadIdx.x == 0) {
            g_bar_ctr[0] = 0;      // per-replay barrier reset
            g_bar_ctr[1] = 0;
        }
        for (int i = i0; i < G3; i += stride) {
            float add = (i < 2 * Hn) ? 1.0f : 0.0f;
            g_bias0[i]      = bih0f[i] + add * bhh0f[i];
            g_bias0[G3 + i] = bih0b[i] + add * bhh0b[i];
            g_bias1[i]      = bih1f[i] + add * bhh1f[i];
            g_bias1[G3 + i] = bih1b[i] + add * bhh1b[i];
        }
    }
}

__global__ void k_xT_split(const float* __restrict__ x,
                           __nv_bfloat16* __restrict__ hi,
                           __nv_bfloat16* __restrict__ lo) {
    size_t total = (size_t)Bn * Sn * INn;
    for (size_t i = (size_t)blockIdx.x * blockDim.x + threadIdx.x; i < total;
         i += (size_t)gridDim.x * blockDim.x) {
        int k = (int)(i % INn);
        size_t tmp = i / INn;
        int s = (int)(tmp % Sn);
        int b = (int)(tmp / Sn);
        float v = x[i];
        __nv_bfloat16 h = __float2bfloat16(v);
        size_t o = ((size_t)s * Bn + b) * INn + k;
        hi[o] = h;
        lo[o] = __float2bfloat16(v - __bfloat162float(h));
    }
}

// ----------------------------------------------------------------------------
// Batched split-bf16 GEMM, 128x128 tile, 512 threads (16 warps, 4M x 4N),
// warp tile 32x32, 3-stage cp.async, ldmatrix fragments.
// ----------------------------------------------------------------------------
__global__ __launch_bounds__(512) void k_gemm(
    const __nv_bfloat16* __restrict__ Ahi, const __nv_bfloat16* __restrict__ Alo,
    size_t aStrZ,
    const __nv_bfloat16* __restrict__ Whi, const __nv_bfloat16* __restrict__ Wlo,
    size_t wStrZ,
    const float* __restrict__ bias, size_t bStrZ,
    float* __restrict__ C, size_t cStrZ,
    int N, int K)
{
    const int z = blockIdx.z;
    Ahi += (size_t)z * aStrZ;  Alo += (size_t)z * aStrZ;
    Whi += (size_t)z * wStrZ;  Wlo += (size_t)z * wStrZ;
    const float* biasz = bias ? (bias + (size_t)z * bStrZ) : nullptr;
    C += (size_t)z * cStrZ;

    const int m0 = blockIdx.y * 128;
    const int n0 = blockIdx.x * 128;

    extern __shared__ __align__(16) __nv_bfloat16 sm[];
    __nv_bfloat16* sA = sm;                     // [3][2][128][40]
    __nv_bfloat16* sW = sm + 3 * 2 * 128 * 40;  // [3][2][128][40]
    const uint32_t sAaddr = smem_u32(sA);
    const uint32_t sWaddr = smem_u32(sW);

    const int tid  = threadIdx.x;
    const int lane = tid & 31;
    const int warp = tid >> 5;
    const int wm = warp & 3;
    const int wn = warp >> 2;
    const int g  = lane >> 2;
    const int tq = lane & 3;

    const int crow = tid >> 2;
    const int ccol = (tid & 3) * 8;
    const int lrow  = lane & 15;
    const int lcol8 = (lane >> 4) * 8;

    float acc[2][4][4];
#pragma unroll
    for (int a = 0; a < 2; a++)
#pragma unroll
        for (int b = 0; b < 4; b++)
#pragma unroll
            for (int c = 0; c < 4; c++) acc[a][b][c] = 0.0f;

    const int nk = K / 32;

    auto copy_chunk = [&](int ci, int st) {
        const int k0 = ci * 32;
        const size_t ao = (size_t)(m0 + crow) * K + k0 + ccol;
        cp16(sA + ((st * 2 + 0) * 128 + crow) * 40 + ccol, Ahi + ao);
        cp16(sA + ((st * 2 + 1) * 128 + crow) * 40 + ccol, Alo + ao);
        const size_t wo = (size_t)(n0 + crow) * K + k0 + ccol;
        cp16(sW + ((st * 2 + 0) * 128 + crow) * 40 + ccol, Whi + wo);
        cp16(sW + ((st * 2 + 1) * 128 + crow) * 40 + ccol, Wlo + wo);
        CP_COMMIT();
    };

    copy_chunk(0, 0);
    copy_chunk(1, 1);

    for (int ci = 0; ci < nk; ci++) {
        const int st = ci % 3;
        CP_WAIT1();
        __syncthreads();
        if (ci + 2 < nk) copy_chunk(ci + 2, (ci + 2) % 3);
        else CP_COMMIT();

#pragma unroll
        for (int kk = 0; kk < 32; kk += 16) {
            uint32_t ah[2][4], al[2][4];
#pragma unroll
            for (int ms = 0; ms < 2; ms++) {
                uint32_t base = ((st * 2 + 0) * 128 + wm * 32 + ms * 16 + lrow) * 40
                                + kk + lcol8;
                ldsm4(ah[ms], sAaddr + base * 2);
                base = ((st * 2 + 1) * 128 + wm * 32 + ms * 16 + lrow) * 40 + kk + lcol8;
                ldsm4(al[ms], sAaddr + base * 2);
            }
            uint32_t bh01[4], bl01[4], bh23[4], bl23[4];
            {
                uint32_t b = ((st * 2 + 0) * 128 + wn * 32 + lrow) * 40 + kk + lcol8;
                ldsm4(bh01, sWaddr + b * 2);
                b = ((st * 2 + 1) * 128 + wn * 32 + lrow) * 40 + kk + lcol8;
                ldsm4(bl01, sWaddr + b * 2);
                b = ((st * 2 + 0) * 128 + wn * 32 + 16 + lrow) * 40 + kk + lcol8;
                ldsm4(bh23, sWaddr + b * 2);
                b = ((st * 2 + 1) * 128 + wn * 32 + 16 + lrow) * 40 + kk + lcol8;
                ldsm4(bl23, sWaddr + b * 2);
            }
#pragma unroll
            for (int ms = 0; ms < 2; ms++) {
                mma_bf16(acc[ms][0], ah[ms], bh01[0], bh01[2]);
                mma_bf16(acc[ms][0], ah[ms], bl01[0], bl01[2]);
                mma_bf16(acc[ms][0], al[ms], bh01[0], bh01[2]);
                mma_bf16(acc[ms][1], ah[ms], bh01[1], bh01[3]);
                mma_bf16(acc[ms][1], ah[ms], bl01[1], bl01[3]);
                mma_bf16(acc[ms][1], al[ms], bh01[1], bh01[3]);
                mma_bf16(acc[ms][2], ah[ms], bh23[0], bh23[2]);
                mma_bf16(acc[ms][2], ah[ms], bl23[0], bl23[2]);
                mma_bf16(acc[ms][2], al[ms], bh23[0], bh23[2]);
                mma_bf16(acc[ms][3], ah[ms], bh23[1], bh23[3]);
                mma_bf16(acc[ms][3], ah[ms], bl23[1], bl23[3]);
                mma_bf16(acc[ms][3], al[ms], bh23[1], bh23[3]);
            }
        }
    }

#pragma unroll
    for (int ms = 0; ms < 2; ms++)
#pragma unroll
        for (int nf = 0; nf < 4; nf++) {
            int col = n0 + wn * 32 + nf * 8 + tq * 2;
            float b0 = biasz ? biasz[col]     : 0.0f;
            float b1 = biasz ? biasz[col + 1] : 0.0f;
            int row = m0 + wm * 32 + ms * 16 + g;
            float* c0 = C + (size_t)row * N + col;
            c0[0] = acc[ms][nf][0] + b0;
            c0[1] = acc[ms][nf][1] + b1;
            float* c1 = C + (size_t)(row + 8) * N + col;
            c1[0] = acc[ms][nf][2] + b0;
            c1[1] = acc[ms][nf][3] + b1;
        }
}

// ----------------------------------------------------------------------------
// Per-direction grid barrier: release-arrival counter + acquire polling.
// No explicit membars; counter monotonic per replay (reset in k_prep).
// ----------------------------------------------------------------------------
__device__ __forceinline__ void grid_barrier(int dir, unsigned target) {
    __syncthreads();
    if (threadIdx.x == 0) {
        unsigned* ctr = &g_bar_ctr[dir];
        asm volatile("red.release.gpu.global.add.u32 [%0], 1;"
                     :: "l"(ctr) : "memory");
        unsigned v;
        while (true) {
            asm volatile("ld.acquire.gpu.global.u32 %0, [%1];"
                         : "=r"(v) : "l"(ctr) : "memory");
            if ((int)(v - target) >= 0) break;
            __nanosleep(32);
        }
    }
    __syncthreads();
}

// ----------------------------------------------------------------------------
// Gate-fused persistent recurrence (R6/R12 proven structure), 512 threads.
// Warps: wk(2 k16-slices per 32-chunk) x wm(4x16 rows) x wn(2x24 cols).
// 3-stage cp.async A ring, padded smem (SWPAD), one grid barrier per step.
// hA double-buffered by step parity. Hidden state h in REGISTERS.
// gi gate inputs prefetched via __ldg before the K loop.
// ----------------------------------------------------------------------------
__global__ __launch_bounds__(RTHREADS) void k_recur(
    const __nv_bfloat16* __restrict__ Whi,  // [2][G3][Hn] permuted rows
    const __nv_bfloat16* __restrict__ Wlo,
    const float* __restrict__ gi,           // [2][SB][G3]
    __nv_bfloat16* __restrict__ hAhi,       // [2 par][2 dir][B][H]
    __nv_bfloat16* __restrict__ hAlo,
    const float* __restrict__ bhh_f, const float* __restrict__ bhh_b,
    __nv_bfloat16* __restrict__ h0hi,       // layer0: [2][SB][H]; else null
    __nv_bfloat16* __restrict__ h0lo,
    float* __restrict__ out,                // layer1: output; else null
    unsigned bar_base)                      // barrier epoch offset for this launch
{
    extern __shared__ __align__(16) char sm_raw[];
    __nv_bfloat16* sWhi = reinterpret_cast<__nv_bfloat16*>(sm_raw);
    __nv_bfloat16* sWlo = sWhi + RB * SWPAD;
    __nv_bfloat16* sAb  = sWlo + RB * SWPAD;           // [3][2][64][40]
    float* sC = reinterpret_cast<float*>(sAb);          // alias, [2][64][49]
    const uint32_t sAaddr  = smem_u32(sAb);
    const uint32_t sWhaddr = smem_u32(sWhi);
    const uint32_t sWladdr = smem_u32(sWlo);

    const int tid  = threadIdx.x;
    const int dir  = blockIdx.x >> 6;
    const int tile = blockIdx.x & 63;
    const int j0   = tile * 16;
    const int p0   = tile * RB;
    const int HAS  = 2 * Bn * Hn;

    const __nv_bfloat16* WhiD = Whi + (size_t)dir * G3 * Hn;
    const __nv_bfloat16* WloD = Wlo + (size_t)dir * G3 * Hn;
    const float* bhh = dir ? bhh_b : bhh_f;

    const int lane = tid & 31;
    const int warp = tid >> 5;
    const int wk = warp >> 3;        // k16 slice within 32-chunk
    const int w8 = warp & 7;
    const int wm = w8 & 3;           // 16 M rows
    const int wn = w8 >> 2;          // 24 W cols
    const int kk = wk * 16;
    const int lrow   = lane & 15;
    const int lcol8  = (lane >> 4) * 8;
    const int lrow2  = lane & 7;
    const int lcol82 = ((lane >> 3) & 1) * 8;
    const int g  = lane >> 2;
    const int tq = lane & 3;

    // A-copy mapping: 512 threads -> one cp16 per 32-chunk
    const int cp_p   = tid >> 8;
    const int cp_row = (tid >> 2) & 63;
    const int cp_q   = tid & 3;

    // gate-phase mapping
    const int gj = tid & 15;
    const int gb = tid >> 4;
    const float bias_n = bhh[2 * Hn + j0 + gj];

    // ---- load resident W slice ----
    for (int i = tid; i < RB * (Hn / 8); i += RTHREADS) {
        int row = i >> 7;
        int q   = i & 127;
        const size_t off = (size_t)(p0 + row) * Hn + q * 8;
        cp16(&sWhi[row * SWPAD + q * 8], WhiD + off);
        cp16(&sWlo[row * SWPAD + q * 8], WloD + off);
    }
    CP_COMMIT();

    // ---- zero own split state (both parities) ----
    for (int i = tid; i < Bn * 16; i += RTHREADS) {
        int b = i >> 4, j = i & 15;
        int idx = dir * (Bn * Hn) + b * Hn + j0 + j;
        hAhi[idx] = __float2bfloat16(0.0f);
        hAlo[idx] = __float2bfloat16(0.0f);
        hAhi[HAS + idx] = __float2bfloat16(0.0f);
        hAlo[HAS + idx] = __float2bfloat16(0.0f);
    }
    CP_WAIT0();

    unsigned bar_tgt = bar_base + NBAR;
    grid_barrier(dir, bar_tgt);

    // hidden state in registers: this thread owns (b = gb + e*32, j = j0 + gj)
    float h_reg[2] = {0.0f, 0.0f};

    const __nv_bfloat16* pAhi = nullptr;
    const __nv_bfloat16* pAlo = nullptr;

    auto copyA = [&](int ci, int st) {
        const __nv_bfloat16* src = cp_p ? pAlo : pAhi;
        cp16(&sAb[((st * 2 + cp_p) * 64 + cp_row) * 40 + cp_q * 8],
             src + (size_t)cp_row * Hn + ci * 32 + cp_q * 8);
        CP_COMMIT();
    };

    for (int t = 0; t < Sn; ++t) {
        const int par_r = t & 1;
        const int par_w = par_r ^ 1;
        pAhi = hAhi + (size_t)par_r * HAS + (size_t)dir * Bn * Hn;
        pAlo = hAlo + (size_t)par_r * HAS + (size_t)dir * Bn * Hn;

        float acc[3][4];
#pragma unroll
        for (int i = 0; i < 3; i++)
#pragma unroll
            for (int j = 0; j < 4; j++) acc[i][j] = 0.0f;

        copyA(0, 0);
        copyA(1, 1);

        // gi gate-input prefetch: issued now, consumed after the K loop
        float gir[2][3];
        {
            const float* giT = gi + (size_t)dir * SB * G3 + (size_t)t * Bn * G3;
#pragma unroll
            for (int e = 0; e < 2; e++) {
                const float* p = giT + (size_t)(gb + e * 32) * G3 + j0 + gj;
                gir[e][0] = __ldg(p);
                gir[e][1] = __ldg(p + Hn);
                gir[e][2] = __ldg(p + 2 * Hn);
            }
        }

        for (int ci = 0; ci < 32; ci++) {
            const int st = ci % 3;
            CP_WAIT1();
            __syncthreads();
            if (ci + 2 < 32) copyA(ci + 2, (ci + 2) % 3);
            else CP_COMMIT();

            const int kg = ci * 32 + kk;
            uint32_t ah[4], al[4];
            ldsm4(ah, sAaddr + (((st * 2 + 0) * 64 + wm * 16 + lrow) * 40 + kk + lcol8) * 2);
            ldsm4(al, sAaddr + (((st * 2 + 1) * 64 + wm * 16 + lrow) * 40 + kk + lcol8) * 2);
            uint32_t bh01[4], bl01[4], bh2[2], bl2[2];
            ldsm4(bh01, sWhaddr + ((wn * 24 + lrow) * SWPAD + kg + lcol8) * 2);
            ldsm4(bl01, sWladdr + ((wn * 24 + lrow) * SWPAD + kg + lcol8) * 2);
            ldsm2(bh2,  sWhaddr + ((wn * 24 + 16 + lrow2) * SWPAD + kg + lcol82) * 2);
            ldsm2(bl2,  sWladdr + ((wn * 24 + 16 + lrow2) * SWPAD + kg + lcol82) * 2);

            mma_bf16(acc[0], ah, bh01[0], bh01[2]);
            mma_bf16(acc[0], ah, bl01[0], bl01[2]);
            mma_bf16(acc[0], al, bh01[0], bh01[2]);
            mma_bf16(acc[1], ah, bh01[1], bh01[3]);
            mma_bf16(acc[1], ah, bl01[1], bl01[3]);
            mma_bf16(acc[1], al, bh01[1], bh01[3]);
            mma_bf16(acc[2], ah, bh2[0], bh2[1]);
            mma_bf16(acc[2], ah, bl2[0], bl2[1]);
            mma_bf16(acc[2], al, bh2[0], bh2[1]);
        }

        // ---- epilogue: wk partials -> sC0/sC1 (alias A ring) ----
        __syncthreads();
        float* sC0 = sC;
        float* sC1 = sC + 64 * 49;
        {
            float* d = wk ? sC1 : sC0;
#pragma unroll
            for (int nf = 0; nf < 3; nf++) {
                int col = wn * 24 + nf * 8 + tq * 2;
                int row = wm * 16 + g;
                d[row * 49 + col]           = acc[nf][0];
                d[row * 49 + col + 1]       = acc[nf][1];
                d[(row + 8) * 49 + col]     = acc[nf][2];
                d[(row + 8) * 49 + col + 1] = acc[nf][3];
            }
        }
        __syncthreads();

        // ---- gate update for own (dir, all b, j0+gj) ----
        __nv_bfloat16* wAhi = hAhi + (size_t)par_w * HAS + (size_t)dir * Bn * Hn;
        __nv_bfloat16* wAlo = hAlo + (size_t)par_w * HAS + (size_t)dir * Bn * Hn;
#pragma unroll
        for (int e = 0; e < 2; e++) {
            const int b = gb + e * 32;
            const float* c0 = sC0 + b * 49;
            const float* c1 = sC1 + b * 49;
            float hr  = c0[gj]      + c1[gj];
            float hz  = c0[16 + gj] + c1[16 + gj];
            float hn  = c0[32 + gj] + c1[32 + gj] + bias_n;
            float h   = h_reg[e];

            float r  = fsigmoid(gir[e][0] + hr);
            float zz = fsigmoid(gir[e][1] + hz);
            float n  = tanhf(gir[e][2] + r * hn);
            float hnew = (1.0f - zz) * n + zz * h;

            h_reg[e] = hnew;
            __nv_bfloat16 hi = __float2bfloat16(hnew);
            __nv_bfloat16 lo = __float2bfloat16(hnew - __bfloat162float(hi));
            const int widx = b * Hn + j0 + gj;
            wAhi[widx] = hi;
            wAlo[widx] = lo;
            if (h0hi) {
                size_t o = (size_t)dir * SB * Hn + ((size_t)t * Bn + b) * Hn + j0 + gj;
                h0hi[o] = hi;
                h0lo[o] = lo;
            }
            if (out) {
                out[((size_t)b * Sn + t) * (2 * Hn) + (size_t)dir * Hn + j0 + gj] = hnew;
                if (t == Sn - 1)
                    out[(size_t)Bn * Sn * 2 * Hn + (size_t)b * 2 * Hn
                        + (size_t)dir * Hn + j0 + gj] = hnew;
            }
        }

        bar_tgt += NBAR;
        grid_barrier(dir, bar_tgt);
    }
}

// ----------------------------------------------------------------------------
// Launcher
// ----------------------------------------------------------------------------
extern "C" void kernel_launch(void* const* d_in, const int* in_sizes, int n_in,
                              void* d_out, int out_size) {
    const float* x      = (const float*)d_in[0];
    const float* w_ih0f = (const float*)d_in[1];
    const float* w_hh0f = (const float*)d_in[2];
    const float* b_ih0f = (const float*)d_in[3];
    const float* b_hh0f = (const float*)d_in[4];
    const float* w_ih0b = (const float*)d_in[5];
    const float* w_hh0b = (const float*)d_in[6];
    const float* b_ih0b = (const float*)d_in[7];
    const float* b_hh0b = (const float*)d_in[8];
    const float* w_ih1f = (const float*)d_in[9];
    const float* w_hh1f = (const float*)d_in[10];
    const float* b_ih1f = (const float*)d_in[11];
    const float* b_hh1f = (const float*)d_in[12];
    const float* w_ih1b = (const float*)d_in[13];
    const float* w_hh1b = (const float*)d_in[14];
    const float* b_ih1b = (const float*)d_in[15];
    const float* b_hh1b = (const float*)d_in[16];
    float* out = (float*)d_out;

    float *gi, *bias0, *bias1;
    __nv_bfloat16 *xhi, *xlo, *h0hi, *h0lo, *hAhi, *hAlo;
    __nv_bfloat16 *wih0h, *wih0l, *whh0h, *whh0l, *wih1h, *wih1l, *whh1h, *whh1l;
    cudaGetSymbolAddress((void**)&xhi,   g_x_hi);
    cudaGetSymbolAddress((void**)&xlo,   g_x_lo);
    cudaGetSymbolAddress((void**)&gi,    g_gi);
    cudaGetSymbolAddress((void**)&h0hi,  g_h0_hi);
    cudaGetSymbolAddress((void**)&h0lo,  g_h0_lo);
    cudaGetSymbolAddress((void**)&hAhi,  g_hA_hi);
    cudaGetSymbolAddress((void**)&hAlo,  g_hA_lo);
    cudaGetSymbolAddress((void**)&bias0, g_bias0);
    cudaGetSymbolAddress((void**)&bias1, g_bias1);
    cudaGetSymbolAddress((void**)&wih0h, g_wih0_hi);
    cudaGetSymbolAddress((void**)&wih0l, g_wih0_lo);
    cudaGetSymbolAddress((void**)&whh0h, g_whh0_hi);
    cudaGetSymbolAddress((void**)&whh0l, g_whh0_lo);
    cudaGetSymbolAddress((void**)&wih1h, g_wih1_hi);
    cudaGetSymbolAddress((void**)&wih1l, g_wih1_lo);
    cudaGetSymbolAddress((void**)&whh1h, g_whh1_hi);
    cudaGetSymbolAddress((void**)&whh1l, g_whh1_lo);

    const int SMEM_RECUR = (2 * RB * SWPAD + 3 * 2 * 64 * 40) * (int)sizeof(__nv_bfloat16);
    const int SMEM_GEMM  = (3 * 2 * 128 * 40 * 2) * (int)sizeof(__nv_bfloat16);
    static bool attr_done = false;
    if (!attr_done) {
        cudaFuncSetAttribute(k_recur, cudaFuncAttributeMaxDynamicSharedMemorySize, SMEM_RECUR);
        cudaFuncSetAttribute(k_gemm,  cudaFuncAttributeMaxDynamicSharedMemorySize, SMEM_GEMM);
        attr_done = true;
    }

    k_prep<<<dim3(2048, 9), 256>>>(
        w_ih0f, w_ih0b, w_ih1f, w_ih1b, w_hh0f, w_hh0b, w_hh1f, w_hh1b,
        b_ih0f, b_hh0f, b_ih0b, b_hh0b, b_ih1f, b_hh1f, b_ih1b, b_hh1b);
    k_xT_split<<<2048, 256>>>(x, xhi, xlo);

    // layer 0: batched input projection (x shared across dirs)
    k_gemm<<<dim3(G3 / 128, SB / 128, 2), 512, SMEM_GEMM>>>(
        xhi, xlo, 0,
        wih0h, wih0l, (size_t)G3 * INn,
        bias0, G3, gi, (size_t)SB * G3, G3, INn);

    // layer 0 recurrence (barrier epochs [0, 513*NBAR))
    k_recur<<<NRBLK, RTHREADS, SMEM_RECUR>>>(
        whh0h, whh0l, gi, hAhi, hAlo,
        b_hh0f, b_hh0b, h0hi, h0lo, nullptr, 0u);

    // layer 1: batched input projection (per-dir A)
    k_gemm<<<dim3(G3 / 128, SB / 128, 2), 512, SMEM_GEMM>>>(
        h0hi, h0lo, (size_t)SB * Hn,
        wih1h, wih1l, (size_t)G3 * Hn,
        bias1, G3, gi, (size_t)SB * G3, G3, Hn);

    // layer 1 recurrence (barrier epochs continue from layer 0)
    k_recur<<<NRBLK, RTHREADS, SMEM_RECUR>>>(
        whh1h, whh1l, gi, hAhi, hAlo,
        b_hh1f, b_hh1b, nullptr, nullptr, out,
        (unsigned)((Sn + 1) * NBAR));
}